// round 13
// baseline (speedup 1.0000x reference)
#include <cuda_runtime.h>

// PLIF spiking neuron forward — round 13: champion kernel, single change:
// stores use DEFAULT write-back policy (st.global.v8.f32, no .cs) so dirty
// sectors linger in L2 and the L2->DRAM writeback engine drains them in
// long hardware-scheduled bursts. Loads stay .cs (single-use, evict-first).
// Mechanism class: MC burst run-length — the only lever that ever won here.
// x: [B=16, T=32, C=128, H=32, W=32] fp32; a scalar; out spikes fp32 {0,1}.

constexpr int B = 16;
constexpr int T = 32;
constexpr int C = 128;
constexpr int H = 32;
constexpr int W = 32;
constexpr int CHW      = C * H * W;          // 131072 floats per (b,t) slice
constexpr int CHW_V8   = CHW / 8;            // 16384 v8 chunks per slice
constexpr int TOTAL_V8 = B * CHW_V8;         // 262144 v8 sites
constexpr int UNROLL   = 8;

__device__ __forceinline__ void ldg256_cs(const float* p, float* v)
{
    asm volatile(
        "ld.global.cs.v8.f32 {%0,%1,%2,%3,%4,%5,%6,%7}, [%8];"
        : "=f"(v[0]), "=f"(v[1]), "=f"(v[2]), "=f"(v[3]),
          "=f"(v[4]), "=f"(v[5]), "=f"(v[6]), "=f"(v[7])
        : "l"(p));
}

__device__ __forceinline__ void stg256_wb(float* p, const float* v)
{
    asm volatile(
        "st.global.v8.f32 [%0], {%1,%2,%3,%4,%5,%6,%7,%8};"
        :: "l"(p),
           "f"(v[0]), "f"(v[1]), "f"(v[2]), "f"(v[3]),
           "f"(v[4]), "f"(v[5]), "f"(v[6]), "f"(v[7])
        : "memory");
}

__global__ __launch_bounds__(256)
void plif_fwd_kernel(const float* __restrict__ x,
                     const float* __restrict__ a,
                     float*       __restrict__ out)
{
    int i = blockIdx.x * blockDim.x + threadIdx.x;
    if (i >= TOTAL_V8) return;

    int b    = i >> 14;                // i / CHW_V8
    int chw8 = i & (CHW_V8 - 1);
    long long base = (long long)b * (T * CHW) + (long long)chw8 * 8;

    float av = __ldg(a);
    float decay = 1.0f / (1.0f + expf(-av));

    float mem[8];
    #pragma unroll
    for (int e = 0; e < 8; e++) mem[e] = 0.0f;

    #pragma unroll
    for (int tb = 0; tb < T; tb += UNROLL) {
        float xi[UNROLL][8];

        // Phase 1 — read burst: 8 independent LDG.E.256 (8KB/warp).
        #pragma unroll
        for (int u = 0; u < UNROLL; u++)
            ldg256_cs(x + base + (long long)(tb + u) * CHW, xi[u]);

        // Phase 2 — recurrence + spike + hard reset, spikes in place.
        #pragma unroll
        for (int u = 0; u < UNROLL; u++) {
            #pragma unroll
            for (int e = 0; e < 8; e++) {
                mem[e] = fmaf(decay, mem[e], xi[u][e]);
                bool fire = (mem[e] >= 1.0f);
                xi[u][e] = fire ? 1.0f : 0.0f;
                mem[e]   = fire ? 0.0f : mem[e];
            }
        }

        // Phase 3 — write burst: 8 back-to-back STG.E.256, write-back policy.
        #pragma unroll
        for (int u = 0; u < UNROLL; u++)
            stg256_wb(out + base + (long long)(tb + u) * CHW, xi[u]);
    }
}

extern "C" void kernel_launch(void* const* d_in, const int* in_sizes, int n_in,
                              void* d_out, int out_size)
{
    const float* x   = (const float*)d_in[0];
    const float* a   = (const float*)d_in[1];
    float*       out = (float*)d_out;

    constexpr int THREADS = 256;
    constexpr int BLOCKS  = (TOTAL_V8 + THREADS - 1) / THREADS;  // 1024

    plif_fwd_kernel<<<BLOCKS, THREADS>>>(x, a, out);
}